// round 6
// baseline (speedup 1.0000x reference)
#include <cuda_runtime.h>
#include <cuda_fp16.h>
#include <cstdint>

// ---------------------------------------------------------------------------
// GroupLinear: out[t] = x[t] @ w[g].T ; token t in group g iff offs[g-1]<=t<offs[g]
// T=8192, G=8, K=1024, N=2048, fp32 in/out.
// fp32->fp16 convert (merged kernel), then mma.sync.m16n8k16 (HMMA) GEMM.
// R6: explicit fragment double-buffering in the GEMM mainloop — issue LDSMs
// for ks+1 before MMAs of ks (ptxas had no reg headroom to do this at 125/128).
// ---------------------------------------------------------------------------

#define T_TOK 8192
#define G_GRP 8
#define K_DIM 1024
#define N_DIM 2048

#define BM 128
#define BN 128
#define BK 64                    // fp16 elems per chunk = 128 B/row (SW128)
#define NCHUNK (K_DIM / BK)      // 16
#define STAGES 3

#define A_BYTES (BM * BK * 2)    // 16 KB
#define B_BYTES (BN * BK * 2)    // 16 KB
#define STAGE_BYTES (A_BYTES + B_BYTES)        // 32 KB
#define SMEM_TOTAL (STAGES * STAGE_BYTES)      // 96 KB

#define MAX_MTILES 71            // ceil(T/BM) + (G-1)
#define N_TILES (N_DIM / BN)     // 16

// fp16 scratch (device globals: allocation-free scratch per harness rules)
__device__ __align__(16) __half g_x16[(size_t)T_TOK * K_DIM];
__device__ __align__(16) __half g_w16[(size_t)G_GRP * N_DIM * K_DIM];

// ---------------------------------------------------------------------------
// helpers
// ---------------------------------------------------------------------------
static __device__ __forceinline__ uint32_t smem_u32(const void* p) {
    uint32_t a;
    asm("{ .reg .u64 t; cvta.to.shared.u64 t, %1; cvt.u32.u64 %0, t; }"
        : "=r"(a) : "l"(p));
    return a;
}

// SW128 swizzle on 128B rows, 16B chunks: chunk' = chunk ^ (row & 7)
static __device__ __forceinline__ uint32_t swz(uint32_t base, int row, int chunk) {
    return base + ((uint32_t)row << 7) + ((uint32_t)(chunk ^ (row & 7)) << 4);
}

static __device__ __forceinline__ void cp16(uint32_t dst, const void* src, uint32_t sz) {
    asm volatile("cp.async.cg.shared.global [%0], [%1], 16, %2;"
                 :: "r"(dst), "l"(src), "r"(sz));
}
static __device__ __forceinline__ void cp16f(uint32_t dst, const void* src) {
    asm volatile("cp.async.cg.shared.global [%0], [%1], 16;"
                 :: "r"(dst), "l"(src));
}

#define LDSM_X4(r, addr)                                                     \
    asm volatile("ldmatrix.sync.aligned.m8n8.x4.shared.b16 {%0,%1,%2,%3}, [%4];" \
        : "=r"((r)[0]), "=r"((r)[1]), "=r"((r)[2]), "=r"((r)[3]) : "r"(addr))

#define MMA16816(d, a, b0, b1)                                               \
    asm volatile("mma.sync.aligned.m16n8k16.row.col.f32.f16.f16.f32 "        \
        "{%0,%1,%2,%3}, {%4,%5,%6,%7}, {%8,%9}, {%0,%1,%2,%3};"              \
        : "+f"((d)[0]), "+f"((d)[1]), "+f"((d)[2]), "+f"((d)[3])             \
        : "r"((a)[0]), "r"((a)[1]), "r"((a)[2]), "r"((a)[3]),                \
          "r"(b0), "r"(b1))

// streaming store (evict-first): out is write-only, keep L2 for x16/w16
static __device__ __forceinline__ void st_cs_f2(float* p, float a, float b) {
    float2 v = make_float2(a, b);
    asm volatile("st.global.cs.v2.f32 [%0], {%1, %2};"
                 :: "l"(p), "f"(v.x), "f"(v.y) : "memory");
}

// ---------------------------------------------------------------------------
// merged fp32 -> fp16 conversion kernel: x (8M floats) then w (16M floats)
// ---------------------------------------------------------------------------
#define X_FLOATS (T_TOK * K_DIM)                     // 8 M
#define W_FLOATS (G_GRP * N_DIM * K_DIM)             // 16 M
#define CVT_N8 ((X_FLOATS + W_FLOATS) / 8)           // 3 M iterations of 8 floats

__global__ void cvt_all_kernel(const float* __restrict__ x,
                               const float* __restrict__ w) {
    int i = blockIdx.x * blockDim.x + threadIdx.x;
    const int st = gridDim.x * blockDim.x;
    const int xn8 = X_FLOATS / 8;
    for (; i < CVT_N8; i += st) {
        const float4* s4;
        uint4* d4;
        if (i < xn8) {
            s4 = reinterpret_cast<const float4*>(x) + i * 2;
            d4 = reinterpret_cast<uint4*>(g_x16) + i;
        } else {
            int j = i - xn8;
            s4 = reinterpret_cast<const float4*>(w) + j * 2;
            d4 = reinterpret_cast<uint4*>(g_w16) + j;
        }
        float4 v0 = s4[0];
        float4 v1 = s4[1];
        __half2 h0 = __floats2half2_rn(v0.x, v0.y);
        __half2 h1 = __floats2half2_rn(v0.z, v0.w);
        __half2 h2 = __floats2half2_rn(v1.x, v1.y);
        __half2 h3 = __floats2half2_rn(v1.z, v1.w);
        uint4 o;
        o.x = *reinterpret_cast<uint32_t*>(&h0);
        o.y = *reinterpret_cast<uint32_t*>(&h1);
        o.z = *reinterpret_cast<uint32_t*>(&h2);
        o.w = *reinterpret_cast<uint32_t*>(&h3);
        *d4 = o;
    }
}

// ---------------------------------------------------------------------------
// Grouped GEMM, mma.sync fp16, 256 threads = 8 warps (4m x 2n), warp = 32x64
// ---------------------------------------------------------------------------
extern "C" __global__ void __launch_bounds__(256, 2)
grouped_gemm_hmma(const int* __restrict__ offs, float* __restrict__ out) {
    // ---- map blockIdx.x -> (group, m_start, m_end) from device-side offs ----
    int gidx = blockIdx.x;
    const int n0 = blockIdx.y * BN;
    int g = -1, m_start = 0, m_end = 0, prev = 0;
#pragma unroll
    for (int gi = 0; gi < G_GRP; gi++) {
        int e = offs[gi];
        int mg = e - prev;
        int nt = (mg + BM - 1) >> 7;
        if (g < 0) {
            if (gidx < nt) { g = gi; m_start = prev + (gidx << 7); m_end = e; }
            else gidx -= nt;
        }
        prev = e;
    }
    if (g < 0) return;  // uniform per-CTA

    extern __shared__ __align__(1024) char smem[];
    const uint32_t sb = smem_u32(smem);

    const int tid = threadIdx.x;
    const int lane = tid & 31;
    const int wid = tid >> 5;
    const int wm = wid & 3;        // 0..3  (m warp)
    const int wn = wid >> 2;       // 0..1  (n warp)

    // lane-derived fragment row constants (loop-invariant)
    const int rowA0 = wm * 32 + (lane & 15);           // + mi*16
    const int chA   = lane >> 4;                       // + ks*2
    const int rowB0 = wn * 64 + ((lane >> 4) << 3) + (lane & 7);   // + np*16
    const int chB   = (lane >> 3) & 1;                 // + ks*2

    const __half* xA = g_x16 + (size_t)m_start * K_DIM;
    const __half* wB = g_w16 + ((size_t)g * N_DIM + n0) * K_DIM;

    // ---- producer: load chunk j into stage s (all 256 threads, 8 x 16B each) ----
    auto load_stage = [&](int j, int s) {
        const uint32_t a_base = sb + s * STAGE_BYTES;
        const uint32_t b_base = a_base + A_BYTES;
        const int k0 = j * BK;
#pragma unroll
        for (int p = 0; p < 4; p++) {
            int lin = tid + p * 256;        // 0..1023
            int r = lin >> 3;               // 0..127
            int c = lin & 7;                // 16B chunk
            cp16(swz(a_base, r, c), xA + (size_t)r * K_DIM + k0 + c * 8,
                 (m_start + r < T_TOK) ? 16u : 0u);
            cp16f(swz(b_base, r, c), wB + (size_t)r * K_DIM + k0 + c * 8);
        }
        asm volatile("cp.async.commit_group;" ::: "memory");
    };

    load_stage(0, 0);
    load_stage(1, 1);

    float acc[2][8][4] = {};
    uint32_t af[2][2][4];   // [buf][mi][frag]
    uint32_t bf[2][4][4];   // [buf][np][frag]

    // fragment loaders: all 6 LDSMs for one k16 slice into buffer `b`
    auto load_frags = [&](uint32_t a_base, uint32_t b_base, int ks, int b) {
#pragma unroll
        for (int mi = 0; mi < 2; mi++)
            LDSM_X4(af[b][mi], swz(a_base, rowA0 + mi * 16, ks * 2 + chA));
#pragma unroll
        for (int np = 0; np < 4; np++)
            LDSM_X4(bf[b][np], swz(b_base, rowB0 + np * 16, ks * 2 + chB));
    };

    for (int j = 0; j < NCHUNK; j++) {
        const int s = j % STAGES;
        asm volatile("cp.async.wait_group %0;" :: "n"(STAGES - 2) : "memory");
        __syncthreads();   // stage s data visible; all warps done with stage (j+2)%3

        const uint32_t a_base = sb + s * STAGE_BYTES;
        const uint32_t b_base = a_base + A_BYTES;

        // fragments for ks=0 first, then cp.async issue fills the LDSM gap
        load_frags(a_base, b_base, 0, 0);

        if (j + STAGES - 1 < NCHUNK) load_stage(j + STAGES - 1, (j + STAGES - 1) % STAGES);
        else asm volatile("cp.async.commit_group;" ::: "memory");

#pragma unroll
        for (int ks = 0; ks < 4; ks++) {            // 4 x k16 per chunk
            const int cur = ks & 1;
            if (ks < 3) load_frags(a_base, b_base, ks + 1, cur ^ 1);
#pragma unroll
            for (int mi = 0; mi < 2; mi++)
#pragma unroll
                for (int np = 0; np < 4; np++) {
                    MMA16816(acc[mi][np * 2 + 0], af[cur][mi], bf[cur][np][0], bf[cur][np][1]);
                    MMA16816(acc[mi][np * 2 + 1], af[cur][mi], bf[cur][np][2], bf[cur][np][3]);
                }
        }
    }

    // ---- epilogue: masked fp32 streaming stores ----
#pragma unroll
    for (int mi = 0; mi < 2; mi++) {
        const int r0 = m_start + wm * 32 + mi * 16 + (lane >> 2);
        const int r1 = r0 + 8;
#pragma unroll
        for (int ni = 0; ni < 8; ni++) {
            const int col = n0 + wn * 64 + ni * 8 + (lane & 3) * 2;
            if (r0 < m_end)
                st_cs_f2(out + (size_t)r0 * N_DIM + col,
                         acc[mi][ni][0], acc[mi][ni][1]);
            if (r1 < m_end)
                st_cs_f2(out + (size_t)r1 * N_DIM + col,
                         acc[mi][ni][2], acc[mi][ni][3]);
        }
    }
}

// ---------------------------------------------------------------------------
// kernel_launch
// ---------------------------------------------------------------------------
extern "C" void kernel_launch(void* const* d_in, const int* in_sizes, int n_in,
                              void* d_out, int out_size) {
    const float* x  = (const float*)d_in[0];   // [8192, 1024]
    const float* w  = (const float*)d_in[1];   // [8, 2048, 1024]
    const int* offs = (const int*)d_in[2];     // [8]
    float* out      = (float*)d_out;           // [8192, 2048]

    cudaFuncSetAttribute(grouped_gemm_hmma,
                         cudaFuncAttributeMaxDynamicSharedMemorySize, SMEM_TOTAL);

    cvt_all_kernel<<<4096, 256>>>(x, w);
    grouped_gemm_hmma<<<dim3(MAX_MTILES, N_TILES), 256, SMEM_TOTAL>>>(offs, out);
}

// round 7
// speedup vs baseline: 1.0615x; 1.0615x over previous
#include <cuda_runtime.h>
#include <cuda_fp16.h>
#include <cstdint>

// ---------------------------------------------------------------------------
// GroupLinear: out[t] = x[t] @ w[g].T ; token t in group g iff offs[g-1]<=t<offs[g]
// T=8192, G=8, K=1024, N=2048, fp32 in/out.
// fp32->fp16 convert (merged kernel), then mma.sync.m16n8k16 (HMMA) GEMM.
// R7: crossbar-bound fix — 4-warp CTA (2m x 2n), warp tile 64x64, 2 CTAs/SM.
// LDSM bytes per chunk per CTA: 96KB -> 64KB; 256 regs/thread available so
// acc(128) + double-buffered frags(64) fit without spill.
// ---------------------------------------------------------------------------

#define T_TOK 8192
#define G_GRP 8
#define K_DIM 1024
#define N_DIM 2048

#define BM 128
#define BN 128
#define BK 64                    // fp16 elems per chunk = 128 B/row (SW128)
#define NCHUNK (K_DIM / BK)      // 16
#define STAGES 3

#define A_BYTES (BM * BK * 2)    // 16 KB
#define B_BYTES (BN * BK * 2)    // 16 KB
#define STAGE_BYTES (A_BYTES + B_BYTES)        // 32 KB
#define SMEM_TOTAL (STAGES * STAGE_BYTES)      // 96 KB

#define MAX_MTILES 71            // ceil(T/BM) + (G-1)
#define N_TILES (N_DIM / BN)     // 16

// fp16 scratch (device globals: allocation-free scratch per harness rules)
__device__ __align__(16) __half g_x16[(size_t)T_TOK * K_DIM];
__device__ __align__(16) __half g_w16[(size_t)G_GRP * N_DIM * K_DIM];

// ---------------------------------------------------------------------------
// helpers
// ---------------------------------------------------------------------------
static __device__ __forceinline__ uint32_t smem_u32(const void* p) {
    uint32_t a;
    asm("{ .reg .u64 t; cvta.to.shared.u64 t, %1; cvt.u32.u64 %0, t; }"
        : "=r"(a) : "l"(p));
    return a;
}

// SW128 swizzle on 128B rows, 16B chunks: chunk' = chunk ^ (row & 7)
static __device__ __forceinline__ uint32_t swz(uint32_t base, int row, int chunk) {
    return base + ((uint32_t)row << 7) + ((uint32_t)(chunk ^ (row & 7)) << 4);
}

static __device__ __forceinline__ void cp16(uint32_t dst, const void* src, uint32_t sz) {
    asm volatile("cp.async.cg.shared.global [%0], [%1], 16, %2;"
                 :: "r"(dst), "l"(src), "r"(sz));
}
static __device__ __forceinline__ void cp16f(uint32_t dst, const void* src) {
    asm volatile("cp.async.cg.shared.global [%0], [%1], 16;"
                 :: "r"(dst), "l"(src));
}

#define LDSM_X4(r, addr)                                                     \
    asm volatile("ldmatrix.sync.aligned.m8n8.x4.shared.b16 {%0,%1,%2,%3}, [%4];" \
        : "=r"((r)[0]), "=r"((r)[1]), "=r"((r)[2]), "=r"((r)[3]) : "r"(addr))

#define MMA16816(d, a, b0, b1)                                               \
    asm volatile("mma.sync.aligned.m16n8k16.row.col.f32.f16.f16.f32 "        \
        "{%0,%1,%2,%3}, {%4,%5,%6,%7}, {%8,%9}, {%0,%1,%2,%3};"              \
        : "+f"((d)[0]), "+f"((d)[1]), "+f"((d)[2]), "+f"((d)[3])             \
        : "r"((a)[0]), "r"((a)[1]), "r"((a)[2]), "r"((a)[3]),                \
          "r"(b0), "r"(b1))

// streaming store (evict-first): out is write-only, keep L2 for x16/w16
static __device__ __forceinline__ void st_cs_f2(float* p, float a, float b) {
    float2 v = make_float2(a, b);
    asm volatile("st.global.cs.v2.f32 [%0], {%1, %2};"
                 :: "l"(p), "f"(v.x), "f"(v.y) : "memory");
}

// ---------------------------------------------------------------------------
// merged fp32 -> fp16 conversion kernel: x (8M floats) then w (16M floats)
// ---------------------------------------------------------------------------
#define X_FLOATS (T_TOK * K_DIM)                     // 8 M
#define W_FLOATS (G_GRP * N_DIM * K_DIM)             // 16 M
#define CVT_N8 ((X_FLOATS + W_FLOATS) / 8)           // 3 M iterations of 8 floats

__global__ void cvt_all_kernel(const float* __restrict__ x,
                               const float* __restrict__ w) {
    int i = blockIdx.x * blockDim.x + threadIdx.x;
    const int st = gridDim.x * blockDim.x;
    const int xn8 = X_FLOATS / 8;
    for (; i < CVT_N8; i += st) {
        const float4* s4;
        uint4* d4;
        if (i < xn8) {
            s4 = reinterpret_cast<const float4*>(x) + i * 2;
            d4 = reinterpret_cast<uint4*>(g_x16) + i;
        } else {
            int j = i - xn8;
            s4 = reinterpret_cast<const float4*>(w) + j * 2;
            d4 = reinterpret_cast<uint4*>(g_w16) + j;
        }
        float4 v0 = s4[0];
        float4 v1 = s4[1];
        __half2 h0 = __floats2half2_rn(v0.x, v0.y);
        __half2 h1 = __floats2half2_rn(v0.z, v0.w);
        __half2 h2 = __floats2half2_rn(v1.x, v1.y);
        __half2 h3 = __floats2half2_rn(v1.z, v1.w);
        uint4 o;
        o.x = *reinterpret_cast<uint32_t*>(&h0);
        o.y = *reinterpret_cast<uint32_t*>(&h1);
        o.z = *reinterpret_cast<uint32_t*>(&h2);
        o.w = *reinterpret_cast<uint32_t*>(&h3);
        *d4 = o;
    }
}

// ---------------------------------------------------------------------------
// Grouped GEMM: 128 threads = 4 warps (2m x 2n), warp tile 64x64
// ---------------------------------------------------------------------------
extern "C" __global__ void __launch_bounds__(128, 2)
grouped_gemm_hmma(const int* __restrict__ offs, float* __restrict__ out) {
    // ---- map blockIdx.x -> (group, m_start, m_end) from device-side offs ----
    int gidx = blockIdx.x;
    const int n0 = blockIdx.y * BN;
    int g = -1, m_start = 0, m_end = 0, prev = 0;
#pragma unroll
    for (int gi = 0; gi < G_GRP; gi++) {
        int e = offs[gi];
        int mg = e - prev;
        int nt = (mg + BM - 1) >> 7;
        if (g < 0) {
            if (gidx < nt) { g = gi; m_start = prev + (gidx << 7); m_end = e; }
            else gidx -= nt;
        }
        prev = e;
    }
    if (g < 0) return;  // uniform per-CTA

    extern __shared__ __align__(1024) char smem[];
    const uint32_t sb = smem_u32(smem);

    const int tid = threadIdx.x;
    const int lane = tid & 31;
    const int wid = tid >> 5;
    const int wm = wid & 1;        // 0..1  (m warp: 64 rows)
    const int wn = wid >> 1;       // 0..1  (n warp: 64 cols)

    // lane-derived fragment row constants (loop-invariant)
    const int rowA0 = wm * 64 + (lane & 15);           // + mi*16
    const int chA   = lane >> 4;                       // + ks*2
    const int rowB0 = wn * 64 + ((lane >> 4) << 3) + (lane & 7);   // + np*16
    const int chB   = (lane >> 3) & 1;                 // + ks*2

    const __half* xA = g_x16 + (size_t)m_start * K_DIM;
    const __half* wB = g_w16 + ((size_t)g * N_DIM + n0) * K_DIM;

    // ---- producer: load chunk j into stage s (128 threads, 16 x 16B each) ----
    auto load_stage = [&](int j, int s) {
        const uint32_t a_base = sb + s * STAGE_BYTES;
        const uint32_t b_base = a_base + A_BYTES;
        const int k0 = j * BK;
#pragma unroll
        for (int p = 0; p < 8; p++) {
            int lin = tid + p * 128;        // 0..1023
            int r = lin >> 3;               // 0..127
            int c = lin & 7;                // 16B chunk
            cp16(swz(a_base, r, c), xA + (size_t)r * K_DIM + k0 + c * 8,
                 (m_start + r < T_TOK) ? 16u : 0u);
            cp16f(swz(b_base, r, c), wB + (size_t)r * K_DIM + k0 + c * 8);
        }
        asm volatile("cp.async.commit_group;" ::: "memory");
    };

    load_stage(0, 0);
    load_stage(1, 1);

    float acc[4][8][4] = {};   // [mi 0..3][ni 0..7][frag] : 64x64 warp tile
    uint32_t af[2][4][4];      // [buf][mi][frag]
    uint32_t bf[2][4][4];      // [buf][np][frag]

    // fragment loaders: all 8 LDSMs for one k16 slice into buffer `b`
    auto load_frags = [&](uint32_t a_base, uint32_t b_base, int ks, int b) {
#pragma unroll
        for (int mi = 0; mi < 4; mi++)
            LDSM_X4(af[b][mi], swz(a_base, rowA0 + mi * 16, ks * 2 + chA));
#pragma unroll
        for (int np = 0; np < 4; np++)
            LDSM_X4(bf[b][np], swz(b_base, rowB0 + np * 16, ks * 2 + chB));
    };

    for (int j = 0; j < NCHUNK; j++) {
        const int s = j % STAGES;
        asm volatile("cp.async.wait_group %0;" :: "n"(STAGES - 2) : "memory");
        __syncthreads();   // stage s visible; all warps done with stage (j+2)%3

        const uint32_t a_base = sb + s * STAGE_BYTES;
        const uint32_t b_base = a_base + A_BYTES;

        load_frags(a_base, b_base, 0, 0);

        if (j + STAGES - 1 < NCHUNK) load_stage(j + STAGES - 1, (j + STAGES - 1) % STAGES);
        else asm volatile("cp.async.commit_group;" ::: "memory");

#pragma unroll
        for (int ks = 0; ks < 4; ks++) {            // 4 x k16 per chunk
            const int cur = ks & 1;
            if (ks < 3) load_frags(a_base, b_base, ks + 1, cur ^ 1);
#pragma unroll
            for (int mi = 0; mi < 4; mi++)
#pragma unroll
                for (int np = 0; np < 4; np++) {
                    MMA16816(acc[mi][np * 2 + 0], af[cur][mi], bf[cur][np][0], bf[cur][np][1]);
                    MMA16816(acc[mi][np * 2 + 1], af[cur][mi], bf[cur][np][2], bf[cur][np][3]);
                }
        }
    }

    // ---- epilogue: masked fp32 streaming stores ----
#pragma unroll
    for (int mi = 0; mi < 4; mi++) {
        const int r0 = m_start + wm * 64 + mi * 16 + (lane >> 2);
        const int r1 = r0 + 8;
#pragma unroll
        for (int ni = 0; ni < 8; ni++) {
            const int col = n0 + wn * 64 + ni * 8 + (lane & 3) * 2;
            if (r0 < m_end)
                st_cs_f2(out + (size_t)r0 * N_DIM + col,
                         acc[mi][ni][0], acc[mi][ni][1]);
            if (r1 < m_end)
                st_cs_f2(out + (size_t)r1 * N_DIM + col,
                         acc[mi][ni][2], acc[mi][ni][3]);
        }
    }
}

// ---------------------------------------------------------------------------
// kernel_launch
// ---------------------------------------------------------------------------
extern "C" void kernel_launch(void* const* d_in, const int* in_sizes, int n_in,
                              void* d_out, int out_size) {
    const float* x  = (const float*)d_in[0];   // [8192, 1024]
    const float* w  = (const float*)d_in[1];   // [8, 2048, 1024]
    const int* offs = (const int*)d_in[2];     // [8]
    float* out      = (float*)d_out;           // [8192, 2048]

    cudaFuncSetAttribute(grouped_gemm_hmma,
                         cudaFuncAttributeMaxDynamicSharedMemorySize, SMEM_TOTAL);

    cvt_all_kernel<<<4096, 256>>>(x, w);
    grouped_gemm_hmma<<<dim3(MAX_MTILES, N_TILES), 128, SMEM_TOTAL>>>(offs, out);
}

// round 8
// speedup vs baseline: 1.1366x; 1.0707x over previous
#include <cuda_runtime.h>
#include <cuda_fp16.h>
#include <cstdint>

// ---------------------------------------------------------------------------
// GroupLinear: out[t] = x[t] @ w[g].T ; token t in group g iff offs[g-1]<=t<offs[g]
// T=8192, G=8, K=1024, N=2048, fp32 in/out.
// fp32->fp16 convert (merged kernel), then mma.sync.m16n8k16 (HMMA) GEMM.
// R8: software-pipeline ACROSS the chunk boundary — prefetch ks0 fragments of
// chunk j+1 after wait_group+barrier at the end of iter j, so post-barrier MMAs
// start immediately (kills the ~300cyc/chunk LDSM-burst bubble seen in R7:
// tensor 64.4% with neither HMMA pipe nor crossbar saturated).
// ---------------------------------------------------------------------------

#define T_TOK 8192
#define G_GRP 8
#define K_DIM 1024
#define N_DIM 2048

#define BM 128
#define BN 128
#define BK 64                    // fp16 elems per chunk = 128 B/row (SW128)
#define NCHUNK (K_DIM / BK)      // 16
#define STAGES 3

#define A_BYTES (BM * BK * 2)    // 16 KB
#define B_BYTES (BN * BK * 2)    // 16 KB
#define STAGE_BYTES (A_BYTES + B_BYTES)        // 32 KB
#define SMEM_TOTAL (STAGES * STAGE_BYTES)      // 96 KB

#define MAX_MTILES 71            // ceil(T/BM) + (G-1)
#define N_TILES (N_DIM / BN)     // 16

// fp16 scratch (device globals: allocation-free scratch per harness rules)
__device__ __align__(16) __half g_x16[(size_t)T_TOK * K_DIM];
__device__ __align__(16) __half g_w16[(size_t)G_GRP * N_DIM * K_DIM];

// ---------------------------------------------------------------------------
// helpers
// ---------------------------------------------------------------------------
static __device__ __forceinline__ uint32_t smem_u32(const void* p) {
    uint32_t a;
    asm("{ .reg .u64 t; cvta.to.shared.u64 t, %1; cvt.u32.u64 %0, t; }"
        : "=r"(a) : "l"(p));
    return a;
}

// SW128 swizzle on 128B rows, 16B chunks: chunk' = chunk ^ (row & 7)
static __device__ __forceinline__ uint32_t swz(uint32_t base, int row, int chunk) {
    return base + ((uint32_t)row << 7) + ((uint32_t)(chunk ^ (row & 7)) << 4);
}

static __device__ __forceinline__ void cp16(uint32_t dst, const void* src, uint32_t sz) {
    asm volatile("cp.async.cg.shared.global [%0], [%1], 16, %2;"
                 :: "r"(dst), "l"(src), "r"(sz));
}
static __device__ __forceinline__ void cp16f(uint32_t dst, const void* src) {
    asm volatile("cp.async.cg.shared.global [%0], [%1], 16;"
                 :: "r"(dst), "l"(src));
}

#define LDSM_X4(r, addr)                                                     \
    asm volatile("ldmatrix.sync.aligned.m8n8.x4.shared.b16 {%0,%1,%2,%3}, [%4];" \
        : "=r"((r)[0]), "=r"((r)[1]), "=r"((r)[2]), "=r"((r)[3]) : "r"(addr))

#define MMA16816(d, a, b0, b1)                                               \
    asm volatile("mma.sync.aligned.m16n8k16.row.col.f32.f16.f16.f32 "        \
        "{%0,%1,%2,%3}, {%4,%5,%6,%7}, {%8,%9}, {%0,%1,%2,%3};"              \
        : "+f"((d)[0]), "+f"((d)[1]), "+f"((d)[2]), "+f"((d)[3])             \
        : "r"((a)[0]), "r"((a)[1]), "r"((a)[2]), "r"((a)[3]),                \
          "r"(b0), "r"(b1))

// streaming store (evict-first): out is write-only, keep L2 for x16/w16
static __device__ __forceinline__ void st_cs_f2(float* p, float a, float b) {
    float2 v = make_float2(a, b);
    asm volatile("st.global.cs.v2.f32 [%0], {%1, %2};"
                 :: "l"(p), "f"(v.x), "f"(v.y) : "memory");
}

// ---------------------------------------------------------------------------
// merged fp32 -> fp16 conversion kernel: x (8M floats) then w (16M floats)
// fp32 inputs are read-once: use __ldcs (evict-first) so the fp16 outputs
// (which the GEMM re-reads from L2) aren't evicted by dead fp32 lines.
// ---------------------------------------------------------------------------
#define X_FLOATS (T_TOK * K_DIM)                     // 8 M
#define W_FLOATS (G_GRP * N_DIM * K_DIM)             // 16 M
#define CVT_N8 ((X_FLOATS + W_FLOATS) / 8)           // 3 M iterations of 8 floats

__global__ void cvt_all_kernel(const float* __restrict__ x,
                               const float* __restrict__ w) {
    int i = blockIdx.x * blockDim.x + threadIdx.x;
    const int st = gridDim.x * blockDim.x;
    const int xn8 = X_FLOATS / 8;
    for (; i < CVT_N8; i += st) {
        const float4* s4;
        uint4* d4;
        if (i < xn8) {
            s4 = reinterpret_cast<const float4*>(x) + i * 2;
            d4 = reinterpret_cast<uint4*>(g_x16) + i;
        } else {
            int j = i - xn8;
            s4 = reinterpret_cast<const float4*>(w) + j * 2;
            d4 = reinterpret_cast<uint4*>(g_w16) + j;
        }
        float4 v0 = __ldcs(s4);
        float4 v1 = __ldcs(s4 + 1);
        __half2 h0 = __floats2half2_rn(v0.x, v0.y);
        __half2 h1 = __floats2half2_rn(v0.z, v0.w);
        __half2 h2 = __floats2half2_rn(v1.x, v1.y);
        __half2 h3 = __floats2half2_rn(v1.z, v1.w);
        uint4 o;
        o.x = *reinterpret_cast<uint32_t*>(&h0);
        o.y = *reinterpret_cast<uint32_t*>(&h1);
        o.z = *reinterpret_cast<uint32_t*>(&h2);
        o.w = *reinterpret_cast<uint32_t*>(&h3);
        *d4 = o;
    }
}

// ---------------------------------------------------------------------------
// Grouped GEMM: 128 threads = 4 warps (2m x 2n), warp tile 64x64, 2 CTAs/SM
// ---------------------------------------------------------------------------
extern "C" __global__ void __launch_bounds__(128, 2)
grouped_gemm_hmma(const int* __restrict__ offs, float* __restrict__ out) {
    // ---- map blockIdx.x -> (group, m_start, m_end) from device-side offs ----
    int gidx = blockIdx.x;
    const int n0 = blockIdx.y * BN;
    int g = -1, m_start = 0, m_end = 0, prev = 0;
#pragma unroll
    for (int gi = 0; gi < G_GRP; gi++) {
        int e = offs[gi];
        int mg = e - prev;
        int nt = (mg + BM - 1) >> 7;
        if (g < 0) {
            if (gidx < nt) { g = gi; m_start = prev + (gidx << 7); m_end = e; }
            else gidx -= nt;
        }
        prev = e;
    }
    if (g < 0) return;  // uniform per-CTA

    extern __shared__ __align__(1024) char smem[];
    const uint32_t sb = smem_u32(smem);

    const int tid = threadIdx.x;
    const int lane = tid & 31;
    const int wid = tid >> 5;
    const int wm = wid & 1;        // 0..1  (m warp: 64 rows)
    const int wn = wid >> 1;       // 0..1  (n warp: 64 cols)

    // lane-derived fragment row constants (loop-invariant)
    const int rowA0 = wm * 64 + (lane & 15);           // + mi*16
    const int chA   = lane >> 4;                       // + ks*2
    const int rowB0 = wn * 64 + ((lane >> 4) << 3) + (lane & 7);   // + np*16
    const int chB   = (lane >> 3) & 1;                 // + ks*2

    const __half* xA = g_x16 + (size_t)m_start * K_DIM;
    const __half* wB = g_w16 + ((size_t)g * N_DIM + n0) * K_DIM;

    // ---- producer: load chunk j into stage s (128 threads, 16 x 16B each) ----
    auto load_stage = [&](int j, int s) {
        const uint32_t a_base = sb + s * STAGE_BYTES;
        const uint32_t b_base = a_base + A_BYTES;
        const int k0 = j * BK;
#pragma unroll
        for (int p = 0; p < 8; p++) {
            int lin = tid + p * 128;        // 0..1023
            int r = lin >> 3;               // 0..127
            int c = lin & 7;                // 16B chunk
            cp16(swz(a_base, r, c), xA + (size_t)r * K_DIM + k0 + c * 8,
                 (m_start + r < T_TOK) ? 16u : 0u);
            cp16f(swz(b_base, r, c), wB + (size_t)r * K_DIM + k0 + c * 8);
        }
        asm volatile("cp.async.commit_group;" ::: "memory");
    };

    float acc[4][8][4] = {};   // [mi 0..3][ni 0..7][frag] : 64x64 warp tile
    uint32_t af[2][4][4];      // [buf][mi][frag]
    uint32_t bf[2][4][4];      // [buf][np][frag]

    // fragment loaders: all 8 LDSMs for one k16 slice into buffer `b`
    auto load_frags = [&](int s, int ks, int b) {
        const uint32_t a_base = sb + s * STAGE_BYTES;
        const uint32_t b_base = a_base + A_BYTES;
#pragma unroll
        for (int mi = 0; mi < 4; mi++)
            LDSM_X4(af[b][mi], swz(a_base, rowA0 + mi * 16, ks * 2 + chA));
#pragma unroll
        for (int np = 0; np < 4; np++)
            LDSM_X4(bf[b][np], swz(b_base, rowB0 + np * 16, ks * 2 + chB));
    };

    // ---- prologue: stages 0,1 in flight; ks0 frags of chunk 0 in regs ----
    load_stage(0, 0);
    load_stage(1, 1);
    asm volatile("cp.async.wait_group 1;" ::: "memory");   // group 0 done
    __syncthreads();                                       // all threads' writes visible
    load_frags(0, 0, 0);

    for (int j = 0; j < NCHUNK; j++) {
        const int s = j % STAGES;

        // stage (j+2)%3: all reads of it finished before the barrier that
        // ended iter j-1 -> safe to overwrite now
        if (j + STAGES - 1 < NCHUNK) load_stage(j + STAGES - 1, (j + STAGES - 1) % STAGES);
        else asm volatile("cp.async.commit_group;" ::: "memory");

#pragma unroll
        for (int ks = 0; ks < 4; ks++) {            // 4 x k16 per chunk
            const int cur = ks & 1;
            if (ks < 3) load_frags(s, ks + 1, cur ^ 1);
#pragma unroll
            for (int mi = 0; mi < 4; mi++)
#pragma unroll
                for (int np = 0; np < 4; np++) {
                    MMA16816(acc[mi][np * 2 + 0], af[cur][mi], bf[cur][np][0], bf[cur][np][1]);
                    MMA16816(acc[mi][np * 2 + 1], af[cur][mi], bf[cur][np][2], bf[cur][np][3]);
                }
        }

        // cross-chunk prefetch: stage j+1 is complete after wait_group(1);
        // barrier makes every thread's cp.async writes visible, then load
        // ks0 fragments of chunk j+1 so post-barrier MMAs start immediately.
        asm volatile("cp.async.wait_group 1;" ::: "memory");
        __syncthreads();
        if (j + 1 < NCHUNK) load_frags((j + 1) % STAGES, 0, 0);
    }

    // ---- epilogue: masked fp32 streaming stores ----
#pragma unroll
    for (int mi = 0; mi < 4; mi++) {
        const int r0 = m_start + wm * 64 + mi * 16 + (lane >> 2);
        const int r1 = r0 + 8;
#pragma unroll
        for (int ni = 0; ni < 8; ni++) {
            const int col = n0 + wn * 64 + ni * 8 + (lane & 3) * 2;
            if (r0 < m_end)
                st_cs_f2(out + (size_t)r0 * N_DIM + col,
                         acc[mi][ni][0], acc[mi][ni][1]);
            if (r1 < m_end)
                st_cs_f2(out + (size_t)r1 * N_DIM + col,
                         acc[mi][ni][2], acc[mi][ni][3]);
        }
    }
}

// ---------------------------------------------------------------------------
// kernel_launch
// ---------------------------------------------------------------------------
extern "C" void kernel_launch(void* const* d_in, const int* in_sizes, int n_in,
                              void* d_out, int out_size) {
    const float* x  = (const float*)d_in[0];   // [8192, 1024]
    const float* w  = (const float*)d_in[1];   // [8, 2048, 1024]
    const int* offs = (const int*)d_in[2];     // [8]
    float* out      = (float*)d_out;           // [8192, 2048]

    cudaFuncSetAttribute(grouped_gemm_hmma,
                         cudaFuncAttributeMaxDynamicSharedMemorySize, SMEM_TOTAL);

    cvt_all_kernel<<<4096, 256>>>(x, w);
    grouped_gemm_hmma<<<dim3(MAX_MTILES, N_TILES), 128, SMEM_TOTAL>>>(offs, out);
}